// round 2
// baseline (speedup 1.0000x reference)
#include <cuda_runtime.h>

// BlockAttnRes: 8 sources (7 blocks + partial), per-row RMSNorm-scaled logits,
// softmax over the 8 sources, weighted combination of the raw sources.
//
// Shapes: blocks (7,4,2048,1024) f32, partial (4,2048,1024) f32,
//         norm_weight (1024) f32, w (1024) f32 -> out (4,2048,1024) f32.
//
// One CTA per (b,t) row. 256 threads x float4 = 1024 columns. Each input
// element is read exactly once and held in registers through the softmax.

#define NB 7
#define NS 8
#define DIM 1024
#define THREADS 256

// jnp.finfo(float32).eps
__device__ __forceinline__ float feps() { return 1.1920929e-07f; }

// Streaming 128-bit load (evict-first in L1/L2): data has zero reuse.
__device__ __forceinline__ float4 ldcs4(const float* p) {
    return __ldcs(reinterpret_cast<const float4*>(p));
}

__global__ __launch_bounds__(THREADS, 3)
void block_attn_res_kernel(const float* __restrict__ blocks,
                           const float* __restrict__ partial,
                           const float* __restrict__ norm_w,
                           const float* __restrict__ w,
                           float* __restrict__ out,
                           int rows)
{
    const int row  = blockIdx.x;
    const int tid  = threadIdx.x;
    const int lane = tid & 31;
    const int wid  = tid >> 5;

    const size_t col  = (size_t)tid * 4;
    const size_t base = (size_t)row * DIM + col;
    const size_t src_stride = (size_t)rows * DIM;   // one block-source slab

    // wn = w * norm_weight for this thread's 4 columns (reused lines: normal load)
    const float4 wv = *reinterpret_cast<const float4*>(w + col);
    const float4 gv = *reinterpret_cast<const float4*>(norm_w + col);
    const float wn0 = wv.x * gv.x, wn1 = wv.y * gv.y,
                wn2 = wv.z * gv.z, wn3 = wv.w * gv.w;

    // Load all 8 sources for this thread's 4 columns (8 independent loads -> MLP=8)
    float4 v[NS];
#pragma unroll
    for (int n = 0; n < NB; n++)
        v[n] = ldcs4(blocks + (size_t)n * src_stride + base);
    v[NB] = ldcs4(partial + base);

    // Per-thread partials: dot(wn, v_n) and sum(v_n^2)
    float dotp[NS], sqp[NS];
#pragma unroll
    for (int n = 0; n < NS; n++) {
        dotp[n] = wn0 * v[n].x + wn1 * v[n].y + wn2 * v[n].z + wn3 * v[n].w;
        sqp[n]  = v[n].x * v[n].x + v[n].y * v[n].y
                + v[n].z * v[n].z + v[n].w * v[n].w;
    }

    // Warp butterfly reduction of the 16 partials
#pragma unroll
    for (int off = 16; off > 0; off >>= 1) {
#pragma unroll
        for (int n = 0; n < NS; n++) {
            dotp[n] += __shfl_xor_sync(0xffffffffu, dotp[n], off);
            sqp[n]  += __shfl_xor_sync(0xffffffffu, sqp[n],  off);
        }
    }

    __shared__ float red[8][16];     // [warp][0..7 dot, 8..15 sumsq]
    __shared__ float totals[16];
    __shared__ float wgt[NS];

    if (lane == 0) {
#pragma unroll
        for (int n = 0; n < NS; n++) {
            red[wid][n]     = dotp[n];
            red[wid][n + 8] = sqp[n];
        }
    }
    __syncthreads();

    // Threads 0..15 finish the cross-warp sum, one value each
    if (tid < 16) {
        float s = 0.f;
#pragma unroll
        for (int wd = 0; wd < 8; wd++) s += red[wd][tid];
        totals[tid] = s;
    }
    __syncthreads();

    // Thread 0: logits -> softmax weights (8-wide, serial tail ~400 cyc,
    // hidden by the 3 resident CTAs per SM)
    if (tid == 0) {
        float lg[NS];
        float mx = -3.402823466e+38f;
#pragma unroll
        for (int n = 0; n < NS; n++) {
            lg[n] = totals[n] * rsqrtf(totals[n + 8] * (1.0f / DIM) + feps());
            mx = fmaxf(mx, lg[n]);
        }
        float sum = 0.f;
#pragma unroll
        for (int n = 0; n < NS; n++) {
            lg[n] = __expf(lg[n] - mx) ;
            sum += lg[n];
        }
        const float inv = 1.0f / sum;
#pragma unroll
        for (int n = 0; n < NS; n++) wgt[n] = lg[n] * inv;
    }
    __syncthreads();

    // Weighted combination from registers; single float4 streaming store
    float4 o = make_float4(0.f, 0.f, 0.f, 0.f);
#pragma unroll
    for (int n = 0; n < NS; n++) {
        const float a = wgt[n];
        o.x = fmaf(a, v[n].x, o.x);
        o.y = fmaf(a, v[n].y, o.y);
        o.z = fmaf(a, v[n].z, o.z);
        o.w = fmaf(a, v[n].w, o.w);
    }
    __stcs(reinterpret_cast<float4*>(out + base), o);
}

extern "C" void kernel_launch(void* const* d_in, const int* in_sizes, int n_in,
                              void* d_out, int out_size)
{
    const float* blocks  = (const float*)d_in[0];
    const float* partial = (const float*)d_in[1];
    const float* norm_w  = (const float*)d_in[2];
    const float* w       = (const float*)d_in[3];
    float* out = (float*)d_out;

    // rows = B*T, derived from partial's element count (B*T*D)
    const int rows = in_sizes[1] / DIM;

    block_attn_res_kernel<<<rows, THREADS>>>(blocks, partial, norm_w, w, out, rows);
}

// round 4
// speedup vs baseline: 1.0199x; 1.0199x over previous
#include <cuda_runtime.h>

// BlockAttnRes: 8 sources (7 blocks + partial), per-row RMSNorm-scaled logits,
// softmax over the 8 sources, weighted combination of the raw sources.
//
// Shapes (fixed): blocks (7,4,2048,1024) f32, partial (4,2048,1024) f32,
//                 norm_weight (1024) f32, w (1024) f32 -> out (4,2048,1024) f32.
//
// One CTA per (b,t) row. 256 threads x float4 = 1024 columns. Each input
// element is read exactly once and held in registers through the softmax.
// R3: 4 CTAs/SM (const strides free regs), single-__syncthreads epilogue with
// lane-parallel per-warp softmax.

#define NB 7
#define NS 8
#define DIM 1024
#define ROWS 8192            // B*T fixed -> compile-time source stride
#define THREADS 256
#define FULLMASK 0xffffffffu

// jnp.finfo(float32).eps
__device__ __forceinline__ float feps() { return 1.1920929e-07f; }

// Streaming 128-bit load (evict-first): bulk data has zero reuse.
__device__ __forceinline__ float4 ldcs4(const float* p) {
    return __ldcs(reinterpret_cast<const float4*>(p));
}

__global__ __launch_bounds__(THREADS, 4)
void block_attn_res_kernel(const float* __restrict__ blocks,
                           const float* __restrict__ partial,
                           const float* __restrict__ norm_w,
                           const float* __restrict__ w,
                           float* __restrict__ out)
{
    const int tid  = threadIdx.x;
    const int lane = tid & 31;
    const int wid  = tid >> 5;

    const size_t col  = (size_t)tid * 4;
    const size_t base = (size_t)blockIdx.x * DIM + col;
    constexpr size_t SS = (size_t)ROWS * DIM;    // compile-time slab stride

    // wn = w * norm_weight for this thread's 4 columns (reused: normal loads)
    const float4 wv = *reinterpret_cast<const float4*>(w + col);
    const float4 gv = *reinterpret_cast<const float4*>(norm_w + col);
    const float wn0 = wv.x * gv.x, wn1 = wv.y * gv.y,
                wn2 = wv.z * gv.z, wn3 = wv.w * gv.w;

    // 8 independent 16B loads -> MLP=8, constant offsets off one base
    float4 v[NS];
#pragma unroll
    for (int n = 0; n < NB; n++)
        v[n] = ldcs4(blocks + (size_t)n * SS + base);
    v[NB] = ldcs4(partial + base);

    // Per-thread partials: dot(wn, v_n) and sum(v_n^2)
    float dotp[NS], sqp[NS];
#pragma unroll
    for (int n = 0; n < NS; n++) {
        dotp[n] = wn0 * v[n].x + wn1 * v[n].y + wn2 * v[n].z + wn3 * v[n].w;
        sqp[n]  = v[n].x * v[n].x + v[n].y * v[n].y
                + v[n].z * v[n].z + v[n].w * v[n].w;
    }

    // Warp butterfly reduction: all lanes end with the 16 warp sums
#pragma unroll
    for (int off = 16; off > 0; off >>= 1) {
#pragma unroll
        for (int n = 0; n < NS; n++) {
            dotp[n] += __shfl_xor_sync(FULLMASK, dotp[n], off);
            sqp[n]  += __shfl_xor_sync(FULLMASK, sqp[n],  off);
        }
    }

    __shared__ float red[8][16];     // [warp][0..7 dot, 8..15 sumsq]

    if (lane == 0) {
#pragma unroll
        for (int n = 0; n < NS; n++) {
            red[wid][n]     = dotp[n];
            red[wid][n + 8] = sqp[n];
        }
    }
    __syncthreads();                 // the ONLY block-wide barrier

    // Each warp redundantly finishes the cross-warp sum.
    // Lane l owns reduced value (l & 15): 0..7 = dot, 8..15 = sumsq.
    const int l16 = lane & 15;
    float tot = 0.f;
#pragma unroll
    for (int wd = 0; wd < 8; wd++) tot += red[wd][l16];

    // Pair dot (lane n) with sumsq (lane n+8); every lane computes logit for n = lane&7
    const int n8   = lane & 7;
    const float dt = __shfl_sync(FULLMASK, tot, n8);
    const float sq = __shfl_sync(FULLMASK, tot, n8 + 8);
    float lg = dt * rsqrtf(sq * (1.0f / DIM) + feps());

    // Softmax across the 8-lane group (width-8 butterflies)
    float mx = lg;
#pragma unroll
    for (int off = 4; off > 0; off >>= 1)
        mx = fmaxf(mx, __shfl_xor_sync(FULLMASK, mx, off, 8));
    float e = __expf(lg - mx);
    float s = e;
#pragma unroll
    for (int off = 4; off > 0; off >>= 1)
        s += __shfl_xor_sync(FULLMASK, s, off, 8);
    const float myw = e / s;          // weight for source n = lane&7

    // Broadcast the 8 weights to every lane (absolute lanes 0..7 hold them)
    float wgt[NS];
#pragma unroll
    for (int n = 0; n < NS; n++)
        wgt[n] = __shfl_sync(FULLMASK, myw, n);

    // Weighted combination from registers; single streaming float4 store
    float4 o = make_float4(0.f, 0.f, 0.f, 0.f);
#pragma unroll
    for (int n = 0; n < NS; n++) {
        const float a = wgt[n];
        o.x = fmaf(a, v[n].x, o.x);
        o.y = fmaf(a, v[n].y, o.y);
        o.z = fmaf(a, v[n].z, o.z);
        o.w = fmaf(a, v[n].w, o.w);
    }
    __stcs(reinterpret_cast<float4*>(out + base), o);
}

extern "C" void kernel_launch(void* const* d_in, const int* in_sizes, int n_in,
                              void* d_out, int out_size)
{
    const float* blocks  = (const float*)d_in[0];
    const float* partial = (const float*)d_in[1];
    const float* norm_w  = (const float*)d_in[2];
    const float* w       = (const float*)d_in[3];
    float* out = (float*)d_out;

    block_attn_res_kernel<<<ROWS, THREADS>>>(blocks, partial, norm_w, w, out);
}